// round 14
// baseline (speedup 1.0000x reference)
#include <cuda_runtime.h>

#define NN      51
#define HIDN    64
#define HEADS   4
#define DTOT    256     // HEADS*HIDN
#define OUTG    128
#define LH      32
#define NC      8
#define BBATCH  256
#define FFEAT   50
#define GG      (BBATCH*FFEAT)   // 12800
#define SLOPEF  0.01f
#define WPB     8                // warps (graphs) per gat block

// ---------------- scratch (no allocs allowed) ----------------
__device__ float  d_u[16];               // per-head (usrc0,usrc1,udst0,udst1)
__device__ float4 d_vcomb[DTOT];         // (vs, vd, wbar, 0)
__device__ float4 d_WihT0p[NN * 32];     // packed: [n][lane] = W^T[n][lane,+32,+64,+96]
__device__ float4 d_b0p[32];             // packed b0
__device__ float  d_b1[OUTG];
__device__ float  d_xp0[GG * OUTG];      // LSTM layer0 gate pre-activations
__device__ float  d_hseq[GG * LH];       // layer1 hidden outputs

// ---------------- helpers ----------------
__device__ __forceinline__ float fsig(float x) {
    return 1.0f / (1.0f + __expf(-x));
}
__device__ __forceinline__ float ftanhf(float x) {
    float e = __expf(-2.0f * fabsf(x));
    float r = __fdividef(1.0f - e, 1.0f + e);
    return copysignf(r, x);
}

// ---------------- kernel A: precompute (validated, ~6us) ----------------
__global__ void prep_kernel(const float* __restrict__ W1, const float* __restrict__ a1,
                            const float* __restrict__ W2, const float* __restrict__ a2,
                            const float* __restrict__ Wih0,
                            const float* __restrict__ bih0, const float* __restrict__ bhh0,
                            const float* __restrict__ bih1, const float* __restrict__ bhh1) {
    int t = threadIdx.x;   // 128 threads
    int bid = blockIdx.x;
    if (bid < DTOT) {
        __shared__ float rs[3][128];
        int d = bid;
        float w = W2[t * DTOT + d];      // o = t
        rs[0][t] = w * a2[t];
        rs[1][t] = w * a2[OUTG + t];
        rs[2][t] = w;
        __syncthreads();
        if (t < 64) {
            rs[0][t] += rs[0][t + 64];
            rs[1][t] += rs[1][t + 64];
            rs[2][t] += rs[2][t + 64];
        }
        __syncthreads();
        if (t < 32) {
            float v0 = rs[0][t] + rs[0][t + 32];
            float v1 = rs[1][t] + rs[1][t + 32];
            float v2 = rs[2][t] + rs[2][t + 32];
#pragma unroll
            for (int off = 16; off; off >>= 1) {
                v0 += __shfl_down_sync(0xffffffffu, v0, off);
                v1 += __shfl_down_sync(0xffffffffu, v1, off);
                v2 += __shfl_down_sync(0xffffffffu, v2, off);
            }
            if (t == 0) d_vcomb[d] = make_float4(v0, v1, v2 * (1.0f / OUTG), 0.f);
        }
    } else if (bid < DTOT + 13) {
        int idx = (bid - DTOT) * 128 + t;
        if (idx < NN * 32) {
            int n = idx >> 5, l = idx & 31;
            d_WihT0p[idx] = make_float4(Wih0[l * NN + n], Wih0[(l + 32) * NN + n],
                                        Wih0[(l + 64) * NN + n], Wih0[(l + 96) * NN + n]);
        }
    } else {
        if (t < 16) {
            int h = t >> 2, which = t & 3;
            int c = which & 1, side = which >> 1;
            float s = 0.f;
            for (int o = 0; o < HIDN; o++)
                s += W1[(h * HIDN + o) * 2 + c] * a1[h * 2 * HIDN + side * HIDN + o];
            d_u[t] = s;
        }
        if (t < 32)
            d_b0p[t] = make_float4(bih0[t] + bhh0[t], bih0[t + 32] + bhh0[t + 32],
                                   bih0[t + 64] + bhh0[t + 64], bih0[t + 96] + bhh0[t + 96]);
        if (t < OUTG) d_b1[t] = bih1[t] + bhh1[t];
    }
}

// ---------------- kernel B: fused GAT (warp-per-graph) + xp0 ----------------
__global__ void __launch_bounds__(256) gat_kernel(const float* __restrict__ feat,
                                                  const float* __restrict__ W1g) {
    __shared__ float2 W1s[DTOT];
    __shared__ float4 vcomb[DTOT];
    __shared__ float  us[16];
    __shared__ float2 xv[WPB][NN];
    __shared__ float2 PR[WPB][HEADS][NN];
    __shared__ float2 ssm[WPB][HEADS][NN];
    __shared__ float4 P2z[WPB][NN];
    __shared__ float2 Q2[WPB][NN];
    __shared__ float  extsm[WPB][52];

    int t = threadIdx.x, w = t >> 5, lane = t & 31;
    int g = blockIdx.x * WPB + w;

    if (t < DTOT) { W1s[t] = ((const float2*)W1g)[t]; vcomb[t] = d_vcomb[t]; }
    if (t < 16) us[t] = d_u[t];
    {
        const float2* x2 = (const float2*)feat + (size_t)g * NN;
        for (int i = lane; i < NN; i += 32) xv[w][i] = x2[i];
    }
    __syncthreads();

    // stage 1: GAT1 logits + exps
    float2 q[HEADS][2];
#pragma unroll
    for (int h = 0; h < HEADS; h++) {
        float u0 = us[h * 4 + 0], u1 = us[h * 4 + 1], u2 = us[h * 4 + 2], u3 = us[h * 4 + 3];
#pragma unroll
        for (int jb = 0; jb < 2; jb++) {
            int j = jb * 32 + lane;
            float2 xn = (j < NN) ? xv[w][j] : make_float2(0.f, 0.f);
            float es = xn.x * u0 + xn.y * u1;
            float ed = xn.x * u2 + xn.y * u3;
            if (j < NN) PR[w][h][j] = make_float2(__expf(es), __expf(SLOPEF * es));
            q[h][jb] = make_float2(__expf(ed), __expf(SLOPEF * ed));
        }
    }
    __syncwarp();

    // stage 2: attention-weighted feature sums
#pragma unroll
    for (int h = 0; h < HEADS; h++) {
        float2 q0 = q[h][0], q1 = q[h][1];
        float den0 = 0.f, s00 = 0.f, s01 = 0.f;
        float den1 = 0.f, s10 = 0.f, s11 = 0.f;
#pragma unroll 3
        for (int i = 0; i < NN; i++) {
            float2 pr = PR[w][h][i];
            float2 xi = xv[w][i];
            float w0 = fmaxf(pr.x * q0.x, pr.y * q0.y);
            float w1 = fmaxf(pr.x * q1.x, pr.y * q1.y);
            den0 += w0; s00 += w0 * xi.x; s01 += w0 * xi.y;
            den1 += w1; s10 += w1 * xi.x; s11 += w1 * xi.y;
        }
        {
            int j0 = lane;
            float2 pr = PR[w][h][j0]; float2 xj = xv[w][j0];
            float w0 = fmaxf(pr.x * q0.x, pr.y * q0.y);
            den0 -= w0; s00 -= w0 * xj.x; s01 -= w0 * xj.y;
            float inv = __fdividef(1.0f, den0);
            ssm[w][h][j0] = make_float2(s00 * inv, s01 * inv);
        }
        int j1 = 32 + lane;
        if (j1 < NN) {
            float2 pr = PR[w][h][j1]; float2 xj = xv[w][j1];
            float w1 = fmaxf(pr.x * q1.x, pr.y * q1.y);
            den1 -= w1; s10 -= w1 * xj.x; s11 -= w1 * xj.y;
            float inv = __fdividef(1.0f, den1);
            ssm[w][h][j1] = make_float2(s10 * inv, s11 * inv);
        }
    }
    __syncwarp();

    // stage 3: elu(h1) projections -> es2, ed2, zbar
    {
        int grp = lane >> 3, gl = lane & 7;
#pragma unroll 1
        for (int p = 0; p < 13; p++) {
            int j = p * 4 + grp;
            bool valid = (j < NN);
            int jc = valid ? j : 0;
            float2 sh[HEADS];
#pragma unroll
            for (int h = 0; h < HEADS; h++) sh[h] = ssm[w][h][jc];
            float a_es = 0.f, a_ed = 0.f, a_zb = 0.f;
#pragma unroll
            for (int h = 0; h < HEADS; h++) {
                float sx = sh[h].x, sy = sh[h].y;
#pragma unroll
                for (int kk = 0; kk < 8; kk++) {
                    int d = h * 64 + kk * 8 + gl;
                    float2 wv = W1s[d];
                    float h1 = sx * wv.x + sy * wv.y;
                    float he = (h1 > 0.f) ? h1 : (__expf(h1) - 1.0f);
                    float4 vc = vcomb[d];
                    a_es += he * vc.x; a_ed += he * vc.y; a_zb += he * vc.z;
                }
            }
#pragma unroll
            for (int off = 4; off; off >>= 1) {
                a_es += __shfl_down_sync(0xffffffffu, a_es, off);
                a_ed += __shfl_down_sync(0xffffffffu, a_ed, off);
                a_zb += __shfl_down_sync(0xffffffffu, a_zb, off);
            }
            if (gl == 0 && valid) {
                P2z[w][j] = make_float4(__expf(a_es), __expf(SLOPEF * a_es), a_zb, 0.f);
                Q2[w][j] = make_float2(__expf(a_ed), __expf(SLOPEF * a_ed));
            }
        }
    }
    __syncwarp();

    // stage 5: GAT2 attention -> extracted (into smem)
#pragma unroll
    for (int jb = 0; jb < 2; jb++) {
        int j = jb * 32 + lane;
        if (j < NN) {
            float2 qq = Q2[w][j];
            float den = 0.f, acc = 0.f;
#pragma unroll 3
            for (int i = 0; i < NN; i++) {
                float4 p = P2z[w][i];
                float w_ = fmaxf(p.x * qq.x, p.y * qq.y);
                den += w_; acc += w_ * p.z;
            }
            float4 p = P2z[w][j];
            float w_ = fmaxf(p.x * qq.x, p.y * qq.y);
            den -= w_; acc -= w_ * p.z;
            extsm[w][j] = acc * __fdividef(1.0f, den);
        }
    }
    __syncwarp();

    // stage 6: xp0 = ext @ WihT0 + b0 (per-lane 4 cols)
    {
        float4 acc = d_b0p[lane];
#pragma unroll 4
        for (int n = 0; n < NN; n++) {
            float e = extsm[w][n];
            float4 wv = __ldg(&d_WihT0p[n * 32 + lane]);
            acc.x += e * wv.x; acc.y += e * wv.y;
            acc.z += e * wv.z; acc.w += e * wv.w;
        }
        float* xg = d_xp0 + (size_t)g * OUTG;
        xg[lane] = acc.x; xg[lane + 32] = acc.y;
        xg[lane + 64] = acc.z; xg[lane + 96] = acc.w;
    }
}

// ---------------- kernel C: shuffle-resident LSTM, one barrier per step ----------------
// Layer0: warps 0-3 (gate = wid), lane j owns column j of (c0,h0) redundantly.
// Layer1: warps 4-7 (gate = wid-4), lane j owns column j of (c1,h1) redundantly.
// Timeline: step k handles layer0 time k and layer1 time k-2.
__global__ void __launch_bounds__(256) lstm_kernel(const float* __restrict__ Whh0,
                                                   const float* __restrict__ Wih1,
                                                   const float* __restrict__ Whh1) {
    __shared__ float g0buf[2][OUTG];
    __shared__ float g1buf[2][OUTG];
    __shared__ float h0s[2][LH];

    int f = blockIdx.x;    // 50 blocks
    int t = threadIdx.x;   // 256 threads
    int wid = t >> 5, lane = t & 31;
    bool isL0 = (t < OUTG);

    float wreg[32], wreg2[32];
    float bias = 0.f;
    if (isL0) {
#pragma unroll
        for (int m = 0; m < 32; m++) wreg[m] = Whh0[t * 32 + m];
    } else {
        int r = t - OUTG;
#pragma unroll
        for (int m = 0; m < 32; m++) { wreg[m] = Wih1[r * 32 + m]; wreg2[m] = Whh1[r * 32 + m]; }
        bias = d_b1[r];
    }

    float c0 = 0.f, c1 = 0.f, h1v = 0.f;

    // xp pipeline (layer0 threads): 2 outstanding loads
    float ldA = 0.f, ldB = 0.f;
    if (isL0) {
        ldA = d_xp0[(size_t)f * OUTG + t];                       // step 0
        ldB = d_xp0[((size_t)FFEAT + f) * OUTG + t];             // step 1
    }
    __syncthreads();

#pragma unroll 1
    for (int k = 0; k < BBATCH + 3; k++) {
        int p = k & 1;
        if (isL0) {
            // h-update: h0(k-1) from g0buf[1-p]
            float h0v = 0.f;
            if (k >= 1 && k <= BBATCH) {
                float gi = g0buf[1 - p][lane];
                float gf = g0buf[1 - p][32 + lane];
                float gg = g0buf[1 - p][64 + lane];
                float go = g0buf[1 - p][96 + lane];
                c0 = fsig(gf) * c0 + fsig(gi) * ftanhf(gg);
                h0v = fsig(go) * ftanhf(c0);
            }
            if (wid == 0) h0s[p][lane] = h0v;    // publish h0(k-1) for layer1 @ step k+1
            // dot: g0(k) = xp(k) + Whh0 . h0(k-1)
            if (k < BBATCH) {
                float xpv = ldA;
                ldA = ldB;
                if (k + 2 < BBATCH)
                    ldB = __ldcg(&d_xp0[((size_t)(k + 2) * FFEAT + f) * OUTG + t]);
                float a0 = xpv, a1 = 0.f, a2 = 0.f, a3 = 0.f;
#pragma unroll
                for (int m = 0; m < 32; m += 4) {
                    float h0 = __shfl_sync(0xffffffffu, h0v, m);
                    float h1 = __shfl_sync(0xffffffffu, h0v, m + 1);
                    float h2 = __shfl_sync(0xffffffffu, h0v, m + 2);
                    float h3 = __shfl_sync(0xffffffffu, h0v, m + 3);
                    a0 += wreg[m] * h0;
                    a1 += wreg[m + 1] * h1;
                    a2 += wreg[m + 2] * h2;
                    a3 += wreg[m + 3] * h3;
                }
                g0buf[p][t] = (a0 + a1) + (a2 + a3);
            }
        } else {
            // layer1: h-update h1(k-3) from g1buf[1-p]
            if (k >= 3) {
                float gi = g1buf[1 - p][lane];
                float gf = g1buf[1 - p][32 + lane];
                float gg = g1buf[1 - p][64 + lane];
                float go = g1buf[1 - p][96 + lane];
                c1 = fsig(gf) * c1 + fsig(gi) * ftanhf(gg);
                h1v = fsig(go) * ftanhf(c1);
                if (wid == 4)
                    d_hseq[(((size_t)(k - 3)) * FFEAT + f) * LH + lane] = h1v;
            }
            // dot: g1(k-2) = b1 + Wih1 . h0(k-2) + Whh1 . h1(k-3)
            if (k >= 2 && k < BBATCH + 2) {
                float h0old = h0s[1 - p][lane];   // h0(k-2), published @ step k-1
                float a0 = bias, a1 = 0.f, a2 = 0.f, a3 = 0.f;
#pragma unroll
                for (int m = 0; m < 32; m += 2) {
                    float x0 = __shfl_sync(0xffffffffu, h0old, m);
                    float y0 = __shfl_sync(0xffffffffu, h1v, m);
                    float x1 = __shfl_sync(0xffffffffu, h0old, m + 1);
                    float y1 = __shfl_sync(0xffffffffu, h1v, m + 1);
                    a0 += wreg[m] * x0;
                    a1 += wreg2[m] * y0;
                    a2 += wreg[m + 1] * x1;
                    a3 += wreg2[m + 1] * y1;
                }
                g1buf[p][t - OUTG] = (a0 + a1) + (a2 + a3);
            }
        }
        __syncthreads();
    }
}

// ---------------- kernel D: final FC ----------------
__global__ void __launch_bounds__(256) fc_kernel(const float* __restrict__ Wfc,
                                                 const float* __restrict__ bfc,
                                                 float* __restrict__ out) {
    int b = blockIdx.x;          // 256 blocks
    int t = threadIdx.x;
    int k = t >> 5, lane = t & 31;   // 8 warps = 8 classes
    const float* y = d_hseq + (size_t)b * (FFEAT * LH);
    const float* w = Wfc + (size_t)k * (FFEAT * LH);
    float acc = 0.f;
    for (int i = lane; i < FFEAT * LH; i += 32)
        acc += y[i] * w[i];
#pragma unroll
    for (int off = 16; off; off >>= 1)
        acc += __shfl_down_sync(0xffffffffu, acc, off);
    if (lane == 0) out[b * NC + k] = acc + bfc[k];
}

// ---------------- launch: serial, no streams (safe) ----------------
extern "C" void kernel_launch(void* const* d_in, const int* in_sizes, int n_in,
                              void* d_out, int out_size) {
    const float* feat = (const float*)d_in[0];
    const float* W1   = (const float*)d_in[1];
    const float* a1   = (const float*)d_in[2];
    const float* W2   = (const float*)d_in[3];
    const float* a2   = (const float*)d_in[4];
    const float* Wih0 = (const float*)d_in[5];
    const float* Whh0 = (const float*)d_in[6];
    const float* bih0 = (const float*)d_in[7];
    const float* bhh0 = (const float*)d_in[8];
    const float* Wih1 = (const float*)d_in[9];
    const float* Whh1 = (const float*)d_in[10];
    const float* bih1 = (const float*)d_in[11];
    const float* bhh1 = (const float*)d_in[12];
    const float* Wfc  = (const float*)d_in[13];
    const float* bfc  = (const float*)d_in[14];
    float* out = (float*)d_out;

    prep_kernel<<<DTOT + 13 + 1, 128>>>(W1, a1, W2, a2, Wih0, bih0, bhh0, bih1, bhh1);
    gat_kernel<<<GG / WPB, 256>>>(feat, W1);
    lstm_kernel<<<FFEAT, 256>>>(Whh0, Wih1, Whh1);
    fc_kernel<<<BBATCH, 256>>>(Wfc, bfc, out);
}

// round 15
// speedup vs baseline: 1.1130x; 1.1130x over previous
#include <cuda_runtime.h>

#define NN      51
#define HIDN    64
#define HEADS   4
#define DTOT    256     // HEADS*HIDN
#define OUTG    128
#define LH      32
#define NC      8
#define BBATCH  256
#define FFEAT   50
#define GG      (BBATCH*FFEAT)   // 12800
#define SLOPEF  0.01f
#define WPB     8                // warps (graphs) per gat block
#define LSTMB   FFEAT            // lstm blocks (first in grid)

// ---------------- scratch (no allocs allowed) ----------------
__device__ float  d_u[16];               // per-head (usrc0,usrc1,udst0,udst1)
__device__ float4 d_vcomb[DTOT];         // (vs, vd, wbar, 0)
__device__ float4 d_WihT0p[NN * 32];     // packed: [n][lane] = W^T[n][lane,+32,+64,+96]
__device__ float4 d_b0p[32];             // packed b0
__device__ float  d_b1[OUTG];
__device__ float  d_Whh1T[LH * OUTG];    // transposed Whh1: [j][r]
__device__ float  d_xp0[GG * OUTG];      // LSTM layer0 gate pre-activations
__device__ float  d_hseq[GG * LH];       // layer1 hidden outputs
__device__ int    d_cnt[BBATCH];         // per-batch-step completion counters

// ---------------- helpers ----------------
__device__ __forceinline__ float fsig(float x) {
    return 1.0f / (1.0f + __expf(-x));
}
__device__ __forceinline__ float ftanhf(float x) {
    float e = __expf(-2.0f * fabsf(x));
    float r = __fdividef(1.0f - e, 1.0f + e);
    return copysignf(r, x);
}

// ---------------- shared-memory overlays ----------------
struct __align__(16) GatSm {             // ~37.3 KB
    float2 W1s[DTOT];
    float4 vcomb[DTOT];
    float  us[16];
    float2 xv[WPB][NN];
    float2 PRh[WPB][NN];                 // one head at a time
    float2 ssm[WPB][HEADS][NN];
    float4 P2z[WPB][NN];
    float2 Q2[WPB][NN];
    float  extsm[WPB][52];
};
struct __align__(16) LstmSm {            // ~18.3 KB
    float whh1[LH * OUTG];               // Whh1^T [j][r]
    __align__(16) float h0[LH];
    __align__(16) float h1s[LH];
    __align__(16) float g0[OUTG];
    __align__(16) float g1[OUTG];
    __align__(16) float xps[2][OUTG];
};
union SmU { GatSm g; LstmSm l; };

// ---------------- kernel A: precompute (fast, many tiny blocks) ----------------
__global__ void prep_kernel(const float* __restrict__ W1, const float* __restrict__ a1,
                            const float* __restrict__ W2, const float* __restrict__ a2,
                            const float* __restrict__ Wih0, const float* __restrict__ Whh1,
                            const float* __restrict__ bih0, const float* __restrict__ bhh0,
                            const float* __restrict__ bih1, const float* __restrict__ bhh1) {
    int t = threadIdx.x;   // 128 threads
    int bid = blockIdx.x;
    if (bid < DTOT) {
        __shared__ float rs[3][128];
        int d = bid;
        float w = W2[t * DTOT + d];      // o = t
        rs[0][t] = w * a2[t];
        rs[1][t] = w * a2[OUTG + t];
        rs[2][t] = w;
        __syncthreads();
        if (t < 64) {
            rs[0][t] += rs[0][t + 64];
            rs[1][t] += rs[1][t + 64];
            rs[2][t] += rs[2][t + 64];
        }
        __syncthreads();
        if (t < 32) {
            float v0 = rs[0][t] + rs[0][t + 32];
            float v1 = rs[1][t] + rs[1][t + 32];
            float v2 = rs[2][t] + rs[2][t + 32];
#pragma unroll
            for (int off = 16; off; off >>= 1) {
                v0 += __shfl_down_sync(0xffffffffu, v0, off);
                v1 += __shfl_down_sync(0xffffffffu, v1, off);
                v2 += __shfl_down_sync(0xffffffffu, v2, off);
            }
            if (t == 0) d_vcomb[d] = make_float4(v0, v1, v2 * (1.0f / OUTG), 0.f);
        }
    } else if (bid < DTOT + 13) {
        // packed transpose of Wih0: 51*32 float4 items
        int idx = (bid - DTOT) * 128 + t;
        if (idx < NN * 32) {
            int n = idx >> 5, l = idx & 31;
            d_WihT0p[idx] = make_float4(Wih0[l * NN + n], Wih0[(l + 32) * NN + n],
                                        Wih0[(l + 64) * NN + n], Wih0[(l + 96) * NN + n]);
        }
    } else if (bid < DTOT + 13 + 32) {
        // transpose Whh1 -> [j][r]
        int idx = (bid - DTOT - 13) * 128 + t;
        int j = idx >> 7, r = idx & 127;
        d_Whh1T[idx] = Whh1[r * LH + j];
    } else {
        // misc: u, b0p, b1, counters
        if (t < 16) {
            int h = t >> 2, which = t & 3;
            int c = which & 1, side = which >> 1;
            float s = 0.f;
            for (int o = 0; o < HIDN; o++)
                s += W1[(h * HIDN + o) * 2 + c] * a1[h * 2 * HIDN + side * HIDN + o];
            d_u[t] = s;
        }
        if (t < 32)
            d_b0p[t] = make_float4(bih0[t] + bhh0[t], bih0[t + 32] + bhh0[t + 32],
                                   bih0[t + 64] + bhh0[t + 64], bih0[t + 96] + bhh0[t + 96]);
        if (t < OUTG) {
            d_b1[t] = bih1[t] + bhh1[t];
            d_cnt[t] = 0;
            d_cnt[t + OUTG] = 0;   // reset all 256 progress counters
        }
    }
}

// ---------------- GAT role (blocks >= LSTMB) — R5's merged-stage version ----------------
__device__ __forceinline__ void gat_role(GatSm* S, const float* __restrict__ feat,
                                         const float* __restrict__ W1g, int gb) {
    int t = threadIdx.x, w = t >> 5, lane = t & 31;
    int g = gb * WPB + w;

    if (t < DTOT) { S->W1s[t] = ((const float2*)W1g)[t]; S->vcomb[t] = d_vcomb[t]; }
    if (t < 16) S->us[t] = d_u[t];
    {
        const float2* x2 = (const float2*)feat + (size_t)g * NN;
        for (int i = lane; i < NN; i += 32) S->xv[w][i] = x2[i];
    }
    __syncthreads();

    // stages 1+2 merged per head: logits/exps then attention-weighted sums
#pragma unroll 1
    for (int h = 0; h < HEADS; h++) {
        float u0 = S->us[h * 4 + 0], u1 = S->us[h * 4 + 1];
        float u2 = S->us[h * 4 + 2], u3 = S->us[h * 4 + 3];
        float2 q0, q1;
        {
            int j = lane;
            float2 xn = S->xv[w][j];
            float es = xn.x * u0 + xn.y * u1;
            float ed = xn.x * u2 + xn.y * u3;
            S->PRh[w][j] = make_float2(__expf(es), __expf(SLOPEF * es));
            q0 = make_float2(__expf(ed), __expf(SLOPEF * ed));
            int j1 = 32 + lane;
            float2 xn1 = (j1 < NN) ? S->xv[w][j1] : make_float2(0.f, 0.f);
            float es1 = xn1.x * u0 + xn1.y * u1;
            float ed1 = xn1.x * u2 + xn1.y * u3;
            if (j1 < NN) S->PRh[w][j1] = make_float2(__expf(es1), __expf(SLOPEF * es1));
            q1 = make_float2(__expf(ed1), __expf(SLOPEF * ed1));
        }
        __syncwarp();

        float den0 = 0.f, s00 = 0.f, s01 = 0.f;
        float den1 = 0.f, s10 = 0.f, s11 = 0.f;
#pragma unroll 3
        for (int i = 0; i < NN; i++) {
            float2 pr = S->PRh[w][i];
            float2 xi = S->xv[w][i];
            float w0 = fmaxf(pr.x * q0.x, pr.y * q0.y);
            float w1 = fmaxf(pr.x * q1.x, pr.y * q1.y);
            den0 += w0; s00 += w0 * xi.x; s01 += w0 * xi.y;
            den1 += w1; s10 += w1 * xi.x; s11 += w1 * xi.y;
        }
        {
            int j0 = lane;
            float2 pr = S->PRh[w][j0]; float2 xj = S->xv[w][j0];
            float w0 = fmaxf(pr.x * q0.x, pr.y * q0.y);
            den0 -= w0; s00 -= w0 * xj.x; s01 -= w0 * xj.y;
            float inv = __fdividef(1.0f, den0);
            S->ssm[w][h][j0] = make_float2(s00 * inv, s01 * inv);
        }
        int j1 = 32 + lane;
        if (j1 < NN) {
            float2 pr = S->PRh[w][j1]; float2 xj = S->xv[w][j1];
            float w1 = fmaxf(pr.x * q1.x, pr.y * q1.y);
            den1 -= w1; s10 -= w1 * xj.x; s11 -= w1 * xj.y;
            float inv = __fdividef(1.0f, den1);
            S->ssm[w][h][j1] = make_float2(s10 * inv, s11 * inv);
        }
        __syncwarp();
    }

    // stage 3: elu(h1) projections -> es2, ed2, zbar
    {
        int grp = lane >> 3, gl = lane & 7;
#pragma unroll 1
        for (int p = 0; p < 13; p++) {
            int j = p * 4 + grp;
            bool valid = (j < NN);
            int jc = valid ? j : 0;
            float2 sh[HEADS];
#pragma unroll
            for (int h = 0; h < HEADS; h++) sh[h] = S->ssm[w][h][jc];
            float a_es = 0.f, a_ed = 0.f, a_zb = 0.f;
#pragma unroll
            for (int h = 0; h < HEADS; h++) {
                float sx = sh[h].x, sy = sh[h].y;
#pragma unroll
                for (int kk = 0; kk < 8; kk++) {
                    int d = h * 64 + kk * 8 + gl;
                    float2 wv = S->W1s[d];
                    float h1 = sx * wv.x + sy * wv.y;
                    float he = (h1 > 0.f) ? h1 : (__expf(h1) - 1.0f);
                    float4 vc = S->vcomb[d];
                    a_es += he * vc.x; a_ed += he * vc.y; a_zb += he * vc.z;
                }
            }
#pragma unroll
            for (int off = 4; off; off >>= 1) {
                a_es += __shfl_down_sync(0xffffffffu, a_es, off);
                a_ed += __shfl_down_sync(0xffffffffu, a_ed, off);
                a_zb += __shfl_down_sync(0xffffffffu, a_zb, off);
            }
            if (gl == 0 && valid) {
                S->P2z[w][j] = make_float4(__expf(a_es), __expf(SLOPEF * a_es), a_zb, 0.f);
                S->Q2[w][j] = make_float2(__expf(a_ed), __expf(SLOPEF * a_ed));
            }
        }
    }
    __syncwarp();

    // stage 5: GAT2 attention -> extracted (into smem)
#pragma unroll
    for (int jb = 0; jb < 2; jb++) {
        int j = jb * 32 + lane;
        if (j < NN) {
            float2 qq = S->Q2[w][j];
            float den = 0.f, acc = 0.f;
#pragma unroll 3
            for (int i = 0; i < NN; i++) {
                float4 p = S->P2z[w][i];
                float w_ = fmaxf(p.x * qq.x, p.y * qq.y);
                den += w_; acc += w_ * p.z;
            }
            float4 p = S->P2z[w][j];
            float w_ = fmaxf(p.x * qq.x, p.y * qq.y);
            den -= w_; acc -= w_ * p.z;
            S->extsm[w][j] = acc * __fdividef(1.0f, den);
        }
    }
    __syncwarp();

    // stage 6: xp0 = ext @ WihT0 + b0 (per-lane 4 cols), publish counter
    {
        float4 acc = d_b0p[lane];
#pragma unroll 4
        for (int n = 0; n < NN; n++) {
            float e = S->extsm[w][n];
            float4 wv = __ldg(&d_WihT0p[n * 32 + lane]);
            acc.x += e * wv.x; acc.y += e * wv.y;
            acc.z += e * wv.z; acc.w += e * wv.w;
        }
        float* xg = d_xp0 + (size_t)g * OUTG;
        xg[lane] = acc.x; xg[lane + 32] = acc.y;
        xg[lane + 64] = acc.z; xg[lane + 96] = acc.w;
    }
    __threadfence();
    if (lane == 0) atomicAdd(&d_cnt[g / FFEAT], 1);
}

// ---------------- LSTM role (blocks < LSTMB): wa,Wih1 in regs, Whh1 in smem ----------------
__device__ __forceinline__ void lstm_role(LstmSm* S,
                                          const float* __restrict__ Whh0,
                                          const float* __restrict__ Wih1) {
    int f = blockIdx.x;
    int t = threadIdx.x;

    // Whh1^T into smem (coalesced; [j][r] layout -> conflict-free reads)
    for (int i = t; i < LH * OUTG; i += 256) S->whh1[i] = d_Whh1T[i];

    float wa[32];
    if (t < OUTG) {
#pragma unroll
        for (int k = 0; k < 32; k++) wa[k] = Whh0[t * 32 + k];
    } else {
        int r = t - OUTG;
#pragma unroll
        for (int k = 0; k < 32; k++) wa[k] = Wih1[r * 32 + k];
    }
    float b1v = (t >= OUTG) ? d_b1[t - OUTG] : 0.f;
    float c_ = 0.f;
    if (t < LH) { S->h0[t] = 0.f; S->h1s[t] = 0.f; }
    volatile int* vcnt = d_cnt;

    // prologue: xp for steps 0,1 into smem; step 2 into pipeline register
    if (t < OUTG) {
        while (vcnt[0] < FFEAT) __nanosleep(200);
        __threadfence();
        S->xps[0][t] = __ldcg(&d_xp0[(size_t)f * OUTG + t]);
        while (vcnt[1] < FFEAT) __nanosleep(200);
        __threadfence();
        S->xps[1][t] = __ldcg(&d_xp0[((size_t)FFEAT + f) * OUTG + t]);
    }
    float ldreg = 0.f;
    if (t >= 64 && t < 192) {
        while (vcnt[2] < FFEAT) __nanosleep(200);
        __threadfence();
        ldreg = __ldcg(&d_xp0[((size_t)2 * FFEAT + f) * OUTG + (t - 64)]);
    }
    __syncthreads();

    for (int k = 0; k <= BBATCH; k++) {
        // ---- phase A: gate dots (layer0 @ k, layer1 @ k-1) ----
        if (t < OUTG) {
            if (k < BBATCH) {
                const float4* h4 = (const float4*)S->h0;
                float xpv = S->xps[k & 1][t];
                float a0 = 0.f, a1_ = 0.f, a2_ = 0.f, a3 = 0.f;
#pragma unroll
                for (int jj = 0; jj < 8; jj++) {
                    float4 hv = h4[jj];
                    a0 += wa[4 * jj] * hv.x;
                    a1_ += wa[4 * jj + 1] * hv.y;
                    a2_ += wa[4 * jj + 2] * hv.z;
                    a3 += wa[4 * jj + 3] * hv.w;
                }
                S->g0[t] = xpv + ((a0 + a1_) + (a2_ + a3));
            }
        } else if (k >= 1) {
            int r = t - OUTG;
            const float4* h4 = (const float4*)S->h0;
            const float4* h14 = (const float4*)S->h1s;
            float a0 = 0.f, a1_ = 0.f, a2_ = 0.f, a3 = 0.f;
#pragma unroll
            for (int jj = 0; jj < 8; jj++) {
                float4 hv = h4[jj]; float4 hw = h14[jj];
                int base = 4 * jj * OUTG + r;
                a0 += wa[4 * jj] * hv.x + S->whh1[base] * hw.x;
                a1_ += wa[4 * jj + 1] * hv.y + S->whh1[base + OUTG] * hw.y;
                a2_ += wa[4 * jj + 2] * hv.z + S->whh1[base + 2 * OUTG] * hw.z;
                a3 += wa[4 * jj + 3] * hv.w + S->whh1[base + 3 * OUTG] * hw.w;
            }
            S->g1[r] = b1v + ((a0 + a1_) + (a2_ + a3));
        }
        __syncthreads();
        // ---- phase B: state updates + xp prefetch pipeline ----
        if (t < 32) {
            if (k < BBATCH) {
                float gi = S->g0[t], gf = S->g0[32 + t], gg = S->g0[64 + t], go = S->g0[96 + t];
                c_ = fsig(gf) * c_ + fsig(gi) * ftanhf(gg);
                S->h0[t] = fsig(go) * ftanhf(c_);
            }
        } else if (t < 64) {
            if (k >= 1) {
                int r = t - 32;
                float gi = S->g1[r], gf = S->g1[32 + r], gg = S->g1[64 + r], go = S->g1[96 + r];
                c_ = fsig(gf) * c_ + fsig(gi) * ftanhf(gg);
                float hn = fsig(go) * ftanhf(c_);
                S->h1s[r] = hn;
                d_hseq[(((size_t)(k - 1)) * FFEAT + f) * LH + r] = hn;
            }
        } else if (t < 192) {
            int col = t - 64;
            if (k + 2 < BBATCH) S->xps[k & 1][col] = ldreg;   // xp for step k+2
            if (k + 3 < BBATCH) {
                while (vcnt[k + 3] < FFEAT) __nanosleep(200);
                __threadfence();
                ldreg = __ldcg(&d_xp0[((size_t)(k + 3) * FFEAT + f) * OUTG + col]);
            }
        }
        __syncthreads();
    }
}

// ---------------- fused kernel (no cap — natural regalloc) ----------------
__global__ void __launch_bounds__(256) fused_kernel(const float* __restrict__ feat,
                                                    const float* __restrict__ W1g,
                                                    const float* __restrict__ Whh0,
                                                    const float* __restrict__ Wih1) {
    __shared__ __align__(16) char smraw[sizeof(SmU)];
    if (blockIdx.x >= LSTMB) {
        gat_role((GatSm*)smraw, feat, W1g, blockIdx.x - LSTMB);
    } else {
        lstm_role((LstmSm*)smraw, Whh0, Wih1);
    }
}

// ---------------- kernel D: final FC ----------------
__global__ void __launch_bounds__(256) fc_kernel(const float* __restrict__ Wfc,
                                                 const float* __restrict__ bfc,
                                                 float* __restrict__ out) {
    int b = blockIdx.x;
    int t = threadIdx.x;
    int k = t >> 5, lane = t & 31;
    const float* y = d_hseq + (size_t)b * (FFEAT * LH);
    const float* w = Wfc + (size_t)k * (FFEAT * LH);
    float acc = 0.f;
    for (int i = lane; i < FFEAT * LH; i += 32)
        acc += y[i] * w[i];
#pragma unroll
    for (int off = 16; off; off >>= 1)
        acc += __shfl_down_sync(0xffffffffu, acc, off);
    if (lane == 0) out[b * NC + k] = acc + bfc[k];
}

// ---------------- launch ----------------
extern "C" void kernel_launch(void* const* d_in, const int* in_sizes, int n_in,
                              void* d_out, int out_size) {
    const float* feat = (const float*)d_in[0];
    const float* W1   = (const float*)d_in[1];
    const float* a1   = (const float*)d_in[2];
    const float* W2   = (const float*)d_in[3];
    const float* a2   = (const float*)d_in[4];
    const float* Wih0 = (const float*)d_in[5];
    const float* Whh0 = (const float*)d_in[6];
    const float* bih0 = (const float*)d_in[7];
    const float* bhh0 = (const float*)d_in[8];
    const float* Wih1 = (const float*)d_in[9];
    const float* Whh1 = (const float*)d_in[10];
    const float* bih1 = (const float*)d_in[11];
    const float* bhh1 = (const float*)d_in[12];
    const float* Wfc  = (const float*)d_in[13];
    const float* bfc  = (const float*)d_in[14];
    float* out = (float*)d_out;

    prep_kernel<<<DTOT + 13 + 32 + 1, 128>>>(W1, a1, W2, a2, Wih0, Whh1,
                                             bih0, bhh0, bih1, bhh1);
    fused_kernel<<<LSTMB + GG / WPB, 256>>>(feat, W1, Whh0, Wih1);
    fc_kernel<<<BBATCH, 256>>>(Wfc, bfc, out);
}

// round 16
// speedup vs baseline: 1.2528x; 1.1256x over previous
#include <cuda_runtime.h>

#define NN      51
#define HIDN    64
#define HEADS   4
#define DTOT    256     // HEADS*HIDN
#define OUTG    128
#define LH      32
#define NC      8
#define BBATCH  256
#define FFEAT   50
#define GG      (BBATCH*FFEAT)   // 12800
#define SLOPEF  0.01f
#define WPB     8                // warps (graphs) per gat block
#define LSTMB   FFEAT            // lstm blocks (first in grid)

// ---------------- scratch (no allocs allowed) ----------------
__device__ float  d_u[16];               // per-head (usrc0,usrc1,udst0,udst1)
__device__ float4 d_vcomb[DTOT];         // (vs, vd, wbar, 0)
__device__ float4 d_WihT0p[NN * 32];     // packed: [n][lane] = W^T[n][lane,+32,+64,+96]
__device__ float4 d_b0p[32];             // packed b0
__device__ float  d_b1[OUTG];
__device__ float  d_xp0[GG * OUTG];      // LSTM layer0 gate pre-activations
__device__ float  d_hseq[GG * LH];       // layer1 hidden outputs
__device__ int    d_cnt[BBATCH];         // per-batch-step completion counters

// ---------------- helpers ----------------
__device__ __forceinline__ float fsig(float x) {
    return 1.0f / (1.0f + __expf(-x));
}
__device__ __forceinline__ float ftanhf(float x) {
    float e = __expf(-2.0f * fabsf(x));
    float r = __fdividef(1.0f - e, 1.0f + e);
    return copysignf(r, x);
}

// ---------------- shared-memory overlays ----------------
struct __align__(16) GatSm {             // ~37.3 KB
    float2 W1s[DTOT];
    float4 vcomb[DTOT];
    float  us[16];
    float2 xv[WPB][NN];
    float2 PRh[WPB][NN];                 // one head at a time
    float2 ssm[WPB][HEADS][NN];
    float4 P2z[WPB][NN];
    float2 Q2[WPB][NN];
    float  extsm[WPB][52];
};
struct __align__(16) LstmSm {
    __align__(16) float h0[LH];
    __align__(16) float h1s[LH];
    __align__(16) float g0[OUTG];
    __align__(16) float g1[OUTG];
    __align__(16) float xps[2][OUTG];    // double-buffered input projections
};

// ---------------- kernel A: precompute (fast, validated 6.3us) ----------------
__global__ void prep_kernel(const float* __restrict__ W1, const float* __restrict__ a1,
                            const float* __restrict__ W2, const float* __restrict__ a2,
                            const float* __restrict__ Wih0,
                            const float* __restrict__ bih0, const float* __restrict__ bhh0,
                            const float* __restrict__ bih1, const float* __restrict__ bhh1) {
    int t = threadIdx.x;   // 128 threads
    int bid = blockIdx.x;
    if (bid < DTOT) {
        // one block per feature dim d: reduce over o (128 outputs)
        __shared__ float rs[3][128];
        int d = bid;
        float w = W2[t * DTOT + d];      // o = t
        rs[0][t] = w * a2[t];
        rs[1][t] = w * a2[OUTG + t];
        rs[2][t] = w;
        __syncthreads();
        if (t < 64) {
            rs[0][t] += rs[0][t + 64];
            rs[1][t] += rs[1][t + 64];
            rs[2][t] += rs[2][t + 64];
        }
        __syncthreads();
        if (t < 32) {
            float v0 = rs[0][t] + rs[0][t + 32];
            float v1 = rs[1][t] + rs[1][t + 32];
            float v2 = rs[2][t] + rs[2][t + 32];
#pragma unroll
            for (int off = 16; off; off >>= 1) {
                v0 += __shfl_down_sync(0xffffffffu, v0, off);
                v1 += __shfl_down_sync(0xffffffffu, v1, off);
                v2 += __shfl_down_sync(0xffffffffu, v2, off);
            }
            if (t == 0) d_vcomb[d] = make_float4(v0, v1, v2 * (1.0f / OUTG), 0.f);
        }
    } else if (bid < DTOT + 13) {
        // packed transpose of Wih0: 51*32 float4 items
        int idx = (bid - DTOT) * 128 + t;
        if (idx < NN * 32) {
            int n = idx >> 5, l = idx & 31;
            d_WihT0p[idx] = make_float4(Wih0[l * NN + n], Wih0[(l + 32) * NN + n],
                                        Wih0[(l + 64) * NN + n], Wih0[(l + 96) * NN + n]);
        }
    } else {
        // misc: u, b0p, b1, counters
        if (t < 16) {
            int h = t >> 2, which = t & 3;
            int c = which & 1, side = which >> 1;
            float s = 0.f;
            for (int o = 0; o < HIDN; o++)
                s += W1[(h * HIDN + o) * 2 + c] * a1[h * 2 * HIDN + side * HIDN + o];
            d_u[t] = s;
        }
        if (t < 32)
            d_b0p[t] = make_float4(bih0[t] + bhh0[t], bih0[t + 32] + bhh0[t + 32],
                                   bih0[t + 64] + bhh0[t + 64], bih0[t + 96] + bhh0[t + 96]);
        if (t < OUTG) {
            d_b1[t] = bih1[t] + bhh1[t];
            d_cnt[t] = 0;
            d_cnt[t + OUTG] = 0;   // reset all 256 progress counters
        }
    }
}

// ---------------- GAT role (blocks >= LSTMB) — R5's merged-stage version ----------------
__device__ __forceinline__ void gat_role(GatSm* S, const float* __restrict__ feat,
                                         const float* __restrict__ W1g, int gb) {
    int t = threadIdx.x, w = t >> 5, lane = t & 31;
    int g = gb * WPB + w;

    if (t < DTOT) { S->W1s[t] = ((const float2*)W1g)[t]; S->vcomb[t] = d_vcomb[t]; }
    if (t < 16) S->us[t] = d_u[t];
    {
        const float2* x2 = (const float2*)feat + (size_t)g * NN;
        for (int i = lane; i < NN; i += 32) S->xv[w][i] = x2[i];
    }
    __syncthreads();

    // stages 1+2 merged per head: logits/exps then attention-weighted sums
#pragma unroll 1
    for (int h = 0; h < HEADS; h++) {
        float u0 = S->us[h * 4 + 0], u1 = S->us[h * 4 + 1];
        float u2 = S->us[h * 4 + 2], u3 = S->us[h * 4 + 3];
        float2 q0, q1;
        {
            int j = lane;
            float2 xn = S->xv[w][j];
            float es = xn.x * u0 + xn.y * u1;
            float ed = xn.x * u2 + xn.y * u3;
            S->PRh[w][j] = make_float2(__expf(es), __expf(SLOPEF * es));
            q0 = make_float2(__expf(ed), __expf(SLOPEF * ed));
            int j1 = 32 + lane;
            float2 xn1 = (j1 < NN) ? S->xv[w][j1] : make_float2(0.f, 0.f);
            float es1 = xn1.x * u0 + xn1.y * u1;
            float ed1 = xn1.x * u2 + xn1.y * u3;
            if (j1 < NN) S->PRh[w][j1] = make_float2(__expf(es1), __expf(SLOPEF * es1));
            q1 = make_float2(__expf(ed1), __expf(SLOPEF * ed1));
        }
        __syncwarp();

        float den0 = 0.f, s00 = 0.f, s01 = 0.f;
        float den1 = 0.f, s10 = 0.f, s11 = 0.f;
#pragma unroll 3
        for (int i = 0; i < NN; i++) {
            float2 pr = S->PRh[w][i];
            float2 xi = S->xv[w][i];
            float w0 = fmaxf(pr.x * q0.x, pr.y * q0.y);
            float w1 = fmaxf(pr.x * q1.x, pr.y * q1.y);
            den0 += w0; s00 += w0 * xi.x; s01 += w0 * xi.y;
            den1 += w1; s10 += w1 * xi.x; s11 += w1 * xi.y;
        }
        {
            int j0 = lane;
            float2 pr = S->PRh[w][j0]; float2 xj = S->xv[w][j0];
            float w0 = fmaxf(pr.x * q0.x, pr.y * q0.y);
            den0 -= w0; s00 -= w0 * xj.x; s01 -= w0 * xj.y;
            float inv = __fdividef(1.0f, den0);
            S->ssm[w][h][j0] = make_float2(s00 * inv, s01 * inv);
        }
        int j1 = 32 + lane;
        if (j1 < NN) {
            float2 pr = S->PRh[w][j1]; float2 xj = S->xv[w][j1];
            float w1 = fmaxf(pr.x * q1.x, pr.y * q1.y);
            den1 -= w1; s10 -= w1 * xj.x; s11 -= w1 * xj.y;
            float inv = __fdividef(1.0f, den1);
            S->ssm[w][h][j1] = make_float2(s10 * inv, s11 * inv);
        }
        __syncwarp();
    }

    // stage 3: elu(h1) projections -> es2, ed2, zbar
    {
        int grp = lane >> 3, gl = lane & 7;
#pragma unroll 1
        for (int p = 0; p < 13; p++) {
            int j = p * 4 + grp;
            bool valid = (j < NN);
            int jc = valid ? j : 0;
            float2 sh[HEADS];
#pragma unroll
            for (int h = 0; h < HEADS; h++) sh[h] = S->ssm[w][h][jc];
            float a_es = 0.f, a_ed = 0.f, a_zb = 0.f;
#pragma unroll
            for (int h = 0; h < HEADS; h++) {
                float sx = sh[h].x, sy = sh[h].y;
#pragma unroll
                for (int kk = 0; kk < 8; kk++) {
                    int d = h * 64 + kk * 8 + gl;
                    float2 wv = S->W1s[d];
                    float h1 = sx * wv.x + sy * wv.y;
                    float he = (h1 > 0.f) ? h1 : (__expf(h1) - 1.0f);
                    float4 vc = S->vcomb[d];
                    a_es += he * vc.x; a_ed += he * vc.y; a_zb += he * vc.z;
                }
            }
#pragma unroll
            for (int off = 4; off; off >>= 1) {
                a_es += __shfl_down_sync(0xffffffffu, a_es, off);
                a_ed += __shfl_down_sync(0xffffffffu, a_ed, off);
                a_zb += __shfl_down_sync(0xffffffffu, a_zb, off);
            }
            if (gl == 0 && valid) {
                S->P2z[w][j] = make_float4(__expf(a_es), __expf(SLOPEF * a_es), a_zb, 0.f);
                S->Q2[w][j] = make_float2(__expf(a_ed), __expf(SLOPEF * a_ed));
            }
        }
    }
    __syncwarp();

    // stage 5: GAT2 attention -> extracted (into smem)
#pragma unroll
    for (int jb = 0; jb < 2; jb++) {
        int j = jb * 32 + lane;
        if (j < NN) {
            float2 qq = S->Q2[w][j];
            float den = 0.f, acc = 0.f;
#pragma unroll 3
            for (int i = 0; i < NN; i++) {
                float4 p = S->P2z[w][i];
                float w_ = fmaxf(p.x * qq.x, p.y * qq.y);
                den += w_; acc += w_ * p.z;
            }
            float4 p = S->P2z[w][j];
            float w_ = fmaxf(p.x * qq.x, p.y * qq.y);
            den -= w_; acc -= w_ * p.z;
            S->extsm[w][j] = acc * __fdividef(1.0f, den);
        }
    }
    __syncwarp();

    // stage 6: xp0 = ext @ WihT0 + b0 (per-lane 4 cols), publish counter
    {
        float4 acc = d_b0p[lane];
#pragma unroll 4
        for (int n = 0; n < NN; n++) {
            float e = S->extsm[w][n];
            float4 wv = __ldg(&d_WihT0p[n * 32 + lane]);
            acc.x += e * wv.x; acc.y += e * wv.y;
            acc.z += e * wv.z; acc.w += e * wv.w;
        }
        float* xg = d_xp0 + (size_t)g * OUTG;
        xg[lane] = acc.x; xg[lane + 32] = acc.y;
        xg[lane + 64] = acc.z; xg[lane + 96] = acc.w;
    }
    __threadfence();
    if (lane == 0) atomicAdd(&d_cnt[g / FFEAT], 1);
}

// ---------------- LSTM role (blocks < LSTMB) — R5 design, register weights ----------------
__device__ __forceinline__ void lstm_role(LstmSm* S,
                                          const float* __restrict__ Whh0,
                                          const float* __restrict__ Wih1,
                                          const float* __restrict__ Whh1) {
    int f = blockIdx.x;
    int t = threadIdx.x;

    float wa[32], wbv[32];
    if (t < OUTG) {
#pragma unroll
        for (int k = 0; k < 32; k++) wa[k] = Whh0[t * 32 + k];
    } else {
        int r = t - OUTG;
#pragma unroll
        for (int k = 0; k < 32; k++) { wa[k] = Wih1[r * 32 + k]; wbv[k] = Whh1[r * 32 + k]; }
    }
    float b1v = (t >= OUTG) ? d_b1[t - OUTG] : 0.f;
    float c_ = 0.f;
    if (t < LH) { S->h0[t] = 0.f; S->h1s[t] = 0.f; }
    volatile int* vcnt = d_cnt;

    // prologue: xp for steps 0,1 into smem; step 2 into pipeline register
    if (t < OUTG) {
        while (vcnt[0] < FFEAT) __nanosleep(200);
        __threadfence();
        S->xps[0][t] = __ldcg(&d_xp0[(size_t)f * OUTG + t]);
        while (vcnt[1] < FFEAT) __nanosleep(200);
        __threadfence();
        S->xps[1][t] = __ldcg(&d_xp0[((size_t)FFEAT + f) * OUTG + t]);
    }
    float ldreg = 0.f;
    if (t >= 64 && t < 192) {
        while (vcnt[2] < FFEAT) __nanosleep(200);
        __threadfence();
        ldreg = __ldcg(&d_xp0[((size_t)2 * FFEAT + f) * OUTG + (t - 64)]);
    }
    __syncthreads();

    for (int k = 0; k <= BBATCH; k++) {
        // ---- phase A: gate dots (layer0 @ k, layer1 @ k-1) ----
        if (t < OUTG) {
            if (k < BBATCH) {
                const float4* h4 = (const float4*)S->h0;
                float xpv = S->xps[k & 1][t];
                float a0 = 0.f, a1_ = 0.f, a2_ = 0.f, a3 = 0.f;
#pragma unroll
                for (int jj = 0; jj < 8; jj++) {
                    float4 hv = h4[jj];
                    a0 += wa[4 * jj] * hv.x;
                    a1_ += wa[4 * jj + 1] * hv.y;
                    a2_ += wa[4 * jj + 2] * hv.z;
                    a3 += wa[4 * jj + 3] * hv.w;
                }
                S->g0[t] = xpv + ((a0 + a1_) + (a2_ + a3));
            }
        } else if (k >= 1) {
            int r = t - OUTG;
            const float4* h4 = (const float4*)S->h0;
            const float4* h14 = (const float4*)S->h1s;
            float a0 = 0.f, a1_ = 0.f, a2_ = 0.f, a3 = 0.f;
#pragma unroll
            for (int jj = 0; jj < 8; jj++) {
                float4 hv = h4[jj]; float4 hw = h14[jj];
                a0 += wa[4 * jj] * hv.x + wbv[4 * jj] * hw.x;
                a1_ += wa[4 * jj + 1] * hv.y + wbv[4 * jj + 1] * hw.y;
                a2_ += wa[4 * jj + 2] * hv.z + wbv[4 * jj + 2] * hw.z;
                a3 += wa[4 * jj + 3] * hv.w + wbv[4 * jj + 3] * hw.w;
            }
            S->g1[r] = b1v + ((a0 + a1_) + (a2_ + a3));
        }
        __syncthreads();
        // ---- phase B: state updates + xp prefetch pipeline ----
        if (t < 32) {
            if (k < BBATCH) {
                float gi = S->g0[t], gf = S->g0[32 + t], gg = S->g0[64 + t], go = S->g0[96 + t];
                c_ = fsig(gf) * c_ + fsig(gi) * ftanhf(gg);
                S->h0[t] = fsig(go) * ftanhf(c_);
            }
        } else if (t < 64) {
            if (k >= 1) {
                int r = t - 32;
                float gi = S->g1[r], gf = S->g1[32 + r], gg = S->g1[64 + r], go = S->g1[96 + r];
                c_ = fsig(gf) * c_ + fsig(gi) * ftanhf(gg);
                float hn = fsig(go) * ftanhf(c_);
                S->h1s[r] = hn;
                d_hseq[(((size_t)(k - 1)) * FFEAT + f) * LH + r] = hn;
            }
        } else if (t < 192) {
            int col = t - 64;
            if (k + 2 < BBATCH) S->xps[k & 1][col] = ldreg;   // xp for step k+2
            if (k + 3 < BBATCH) {
                while (vcnt[k + 3] < FFEAT) __nanosleep(200);
                __threadfence();
                ldreg = __ldcg(&d_xp0[((size_t)(k + 3) * FFEAT + f) * OUTG + col]);
            }
        }
        __syncthreads();
    }
}

// ---------------- fused kernel: NO register cap (natural ~94-reg allocation) ----------------
__global__ void __launch_bounds__(256) fused_kernel(const float* __restrict__ feat,
                                                    const float* __restrict__ W1g,
                                                    const float* __restrict__ Whh0,
                                                    const float* __restrict__ Wih1,
                                                    const float* __restrict__ Whh1) {
    __shared__ __align__(16) char smraw[sizeof(GatSm)];
    if (blockIdx.x >= LSTMB) {
        gat_role((GatSm*)smraw, feat, W1g, blockIdx.x - LSTMB);
    } else {
        lstm_role((LstmSm*)smraw, Whh0, Wih1, Whh1);
    }
}

// ---------------- kernel D: final FC ----------------
__global__ void __launch_bounds__(256) fc_kernel(const float* __restrict__ Wfc,
                                                 const float* __restrict__ bfc,
                                                 float* __restrict__ out) {
    int b = blockIdx.x;
    int t = threadIdx.x;
    int k = t >> 5, lane = t & 31;
    const float* y = d_hseq + (size_t)b * (FFEAT * LH);
    const float* w = Wfc + (size_t)k * (FFEAT * LH);
    float acc = 0.f;
    for (int i = lane; i < FFEAT * LH; i += 32)
        acc += y[i] * w[i];
#pragma unroll
    for (int off = 16; off; off >>= 1)
        acc += __shfl_down_sync(0xffffffffu, acc, off);
    if (lane == 0) out[b * NC + k] = acc + bfc[k];
}

// ---------------- launch ----------------
extern "C" void kernel_launch(void* const* d_in, const int* in_sizes, int n_in,
                              void* d_out, int out_size) {
    const float* feat = (const float*)d_in[0];
    const float* W1   = (const float*)d_in[1];
    const float* a1   = (const float*)d_in[2];
    const float* W2   = (const float*)d_in[3];
    const float* a2   = (const float*)d_in[4];
    const float* Wih0 = (const float*)d_in[5];
    const float* Whh0 = (const float*)d_in[6];
    const float* bih0 = (const float*)d_in[7];
    const float* bhh0 = (const float*)d_in[8];
    const float* Wih1 = (const float*)d_in[9];
    const float* Whh1 = (const float*)d_in[10];
    const float* bih1 = (const float*)d_in[11];
    const float* bhh1 = (const float*)d_in[12];
    const float* Wfc  = (const float*)d_in[13];
    const float* bfc  = (const float*)d_in[14];
    float* out = (float*)d_out;

    prep_kernel<<<DTOT + 13 + 1, 128>>>(W1, a1, W2, a2, Wih0, bih0, bhh0, bih1, bhh1);
    fused_kernel<<<LSTMB + GG / WPB, 256>>>(feat, W1, Whh0, Wih1, Whh1);
    fc_kernel<<<BBATCH, 256>>>(Wfc, bfc, out);
}